// round 9
// baseline (speedup 1.0000x reference)
#include <cuda_runtime.h>
#include <cuda_fp16.h>
#include <cstdint>

// Problem constants
#define BATCH 8
#define CDIM 256
#define HH 56
#define WW 56
#define HWPIX (HH * WW)          // 3136
#define NHEADS 8
#define HDIM 32
#define SWID 7
#define NSTRIPE (HH / SWID)      // 8
#define NTOK (SWID * WW)         // 392
#define ATTSCALE 0.17677669529663687f  // 32^-0.5

// Scratch (device globals; no allocations allowed). All intermediates f16.
__device__ __half g_xh[BATCH * CDIM * HWPIX];
__device__ __half g_wqh[3 * CDIM * CDIM];
__device__ __half g_wph[CDIM * CDIM];
__device__ __half g_qkvh[BATCH * 3 * CDIM * HWPIX];
__device__ __half g_v2h[BATCH * CDIM * HWPIX];
__device__ __half g_atth[BATCH * CDIM * HWPIX];

__device__ __forceinline__ uint32_t smem_u32(const void* p) {
    return (uint32_t)__cvta_generic_to_shared(p);
}

__device__ __forceinline__ void mma_f16(float c[4], const uint32_t a[4],
                                        const uint32_t b[2]) {
    asm volatile(
        "mma.sync.aligned.m16n8k16.row.col.f32.f16.f16.f32 "
        "{%0,%1,%2,%3}, {%4,%5,%6,%7}, {%8,%9}, {%0,%1,%2,%3};"
        : "+f"(c[0]), "+f"(c[1]), "+f"(c[2]), "+f"(c[3])
        : "r"(a[0]), "r"(a[1]), "r"(a[2]), "r"(a[3]), "r"(b[0]), "r"(b[1]));
}

__device__ __forceinline__ void mma_f16_k8(float c[4], const uint32_t a[2],
                                           uint32_t b) {
    asm volatile(
        "mma.sync.aligned.m16n8k8.row.col.f32.f16.f16.f32 "
        "{%0,%1,%2,%3}, {%4,%5}, {%6}, {%0,%1,%2,%3};"
        : "+f"(c[0]), "+f"(c[1]), "+f"(c[2]), "+f"(c[3])
        : "r"(a[0]), "r"(a[1]), "r"(b));
}

__device__ __forceinline__ void ldsm_x4(uint32_t r[4], uint32_t addr) {
    asm volatile("ldmatrix.sync.aligned.m8n8.x4.shared.b16 {%0,%1,%2,%3}, [%4];"
                 : "=r"(r[0]), "=r"(r[1]), "=r"(r[2]), "=r"(r[3]) : "r"(addr));
}

__device__ __forceinline__ void ldsm_x4_t(uint32_t r[4], uint32_t addr) {
    asm volatile("ldmatrix.sync.aligned.m8n8.x4.trans.shared.b16 {%0,%1,%2,%3}, [%4];"
                 : "=r"(r[0]), "=r"(r[1]), "=r"(r[2]), "=r"(r[3]) : "r"(addr));
}

__device__ __forceinline__ void cp16_ca(void* dst, const void* src, bool pred) {
    int sz = pred ? 16 : 0;
    asm volatile("cp.async.ca.shared.global [%0], [%1], 16, %2;"
                 :: "r"(smem_u32(dst)), "l"(src), "r"(sz));
}
__device__ __forceinline__ void cp16_cg(void* dst, const void* src, bool pred) {
    int sz = pred ? 16 : 0;
    asm volatile("cp.async.cg.shared.global [%0], [%1], 16, %2;"
                 :: "r"(smem_u32(dst)), "l"(src), "r"(sz));
}
#define CP_COMMIT() asm volatile("cp.async.commit_group;")

// ---------------------------------------------------------------------------
// fp32 -> fp16 conversion (4 elems/thread)
// ---------------------------------------------------------------------------
__global__ __launch_bounds__(256) void f2h_kernel(const float* __restrict__ in,
                                                  __half* __restrict__ out, int n)
{
    int id = (blockIdx.x * 256 + threadIdx.x) * 4;
    if (id + 3 < n) {
        float4 v = *(const float4*)&in[id];
        __half2 h0 = __floats2half2_rn(v.x, v.y);
        __half2 h1 = __floats2half2_rn(v.z, v.w);
        uint2 u = {*(uint32_t*)&h0, *(uint32_t*)&h1};
        *(uint2*)&out[id] = u;
    } else {
        for (int i = id; i < n; i++) out[i] = __float2half(in[i]);
    }
}

// ---------------------------------------------------------------------------
// FP16 GEMM, 3-stage cp.async pipeline, dynamic smem. 128x128x32; 8 warps 2x4.
// (unchanged from R8)
// ---------------------------------------------------------------------------
#define ASTR 40
#define BSTR 136
#define GEMM_A_ELEMS (128 * ASTR)
#define GEMM_B_ELEMS (32 * BSTR)
#define GEMM_SMEM ((3 * (GEMM_A_ELEMS + GEMM_B_ELEMS)) * 2)  // 56832 bytes

template<bool HALF_OUT>
__global__ __launch_bounds__(256, 2) void gemm_f16_kernel(
    const __half* __restrict__ X, const __half* __restrict__ W,
    const float* __restrict__ bias, void* __restrict__ OutV,
    int Kdim, int Odim)
{
    const int p0 = blockIdx.x * 128;
    const int o0 = blockIdx.y * 128;
    const int b  = blockIdx.z;

    const __half* Xb = X + (size_t)b * Kdim * HWPIX;

    extern __shared__ __half gsh[];
    __half* Asb = gsh;
    __half* Bsb = gsh + 3 * GEMM_A_ELEMS;

    const int tid = threadIdx.x;
    const int wid = tid >> 5;
    const int lane = tid & 31;
    const int wm = wid & 1;
    const int wn = wid >> 1;
    const int lr = lane >> 2;
    const int lc = lane & 3;

    float acc[4][4][4];
    #pragma unroll
    for (int i = 0; i < 4; i++)
        #pragma unroll
        for (int j = 0; j < 4; j++)
            #pragma unroll
            for (int r = 0; r < 4; r++) acc[i][j][r] = 0.f;

    const int nkt = Kdim / 32;

    auto stage = [&](int kt, int buf) {
        const int k0 = kt * 32;
        __half* As = Asb + buf * GEMM_A_ELEMS;
        __half* Bs = Bsb + buf * GEMM_B_ELEMS;
        #pragma unroll
        for (int i = 0; i < 2; i++) {
            int id = tid * 2 + i;
            int o = id >> 2;
            int c8 = (id & 3) * 8;
            cp16_ca(&As[o * ASTR + c8],
                    &W[(size_t)(o0 + o) * Kdim + k0 + c8], true);
        }
        #pragma unroll
        for (int i = 0; i < 2; i++) {
            int id = tid * 2 + i;
            int row = id >> 4;
            int ch = (id & 15) * 8;
            bool ok = (p0 + ch) < HWPIX;
            int col = ok ? (p0 + ch) : (HWPIX - 8);
            cp16_cg(&Bs[row * BSTR + ch],
                    &Xb[(size_t)(k0 + row) * HWPIX + col], ok);
        }
        CP_COMMIT();
    };

    stage(0, 0);
    if (nkt > 1) stage(1, 1);
    for (int kt = 0; kt < nkt; kt++) {
        const int buf = kt % 3;
        if (kt + 2 < nkt) {
            stage(kt + 2, (kt + 2) % 3);
            asm volatile("cp.async.wait_group 2;");
        } else if (kt + 1 < nkt) {
            asm volatile("cp.async.wait_group 1;");
        } else {
            asm volatile("cp.async.wait_group 0;");
        }
        __syncthreads();

        __half* As = Asb + buf * GEMM_A_ELEMS;
        __half* Bs = Bsb + buf * GEMM_B_ELEMS;

        #pragma unroll
        for (int kk = 0; kk < 32; kk += 16) {
            uint32_t af[4][4];
            #pragma unroll
            for (int mf = 0; mf < 4; mf++) {
                int row = wm * 64 + mf * 16 + (lane & 15);
                int kof = kk + (lane >> 4) * 8;
                ldsm_x4(af[mf], smem_u32(&As[row * ASTR + kof]));
            }
            uint32_t bf[2][4];
            #pragma unroll
            for (int g = 0; g < 2; g++) {
                int krow = kk + (lane & 15);
                int ncol = wn * 32 + g * 16 + (lane >> 4) * 8;
                ldsm_x4_t(bf[g], smem_u32(&Bs[krow * BSTR + ncol]));
            }
            #pragma unroll
            for (int mf = 0; mf < 4; mf++)
                #pragma unroll
                for (int nf = 0; nf < 4; nf++) {
                    uint32_t bb[2] = {bf[nf >> 1][(nf & 1) * 2],
                                      bf[nf >> 1][(nf & 1) * 2 + 1]};
                    mma_f16(acc[mf][nf], af[mf], bb);
                }
        }
        __syncthreads();
    }

    #pragma unroll
    for (int mf = 0; mf < 4; mf++) {
        int m = o0 + wm * 64 + mf * 16 + lr;
        float bv0 = bias[m];
        float bv1 = bias[m + 8];
        #pragma unroll
        for (int nf = 0; nf < 4; nf++) {
            int n = p0 + wn * 32 + nf * 8 + 2 * lc;
            if (n < HWPIX) {
                if (HALF_OUT) {
                    __half* Ob = (__half*)OutV + (size_t)b * Odim * HWPIX;
                    __half2 r0 = __floats2half2_rn(acc[mf][nf][0] + bv0,
                                                   acc[mf][nf][1] + bv0);
                    __half2 r1 = __floats2half2_rn(acc[mf][nf][2] + bv1,
                                                   acc[mf][nf][3] + bv1);
                    *(__half2*)&Ob[(size_t)m * HWPIX + n] = r0;
                    *(__half2*)&Ob[(size_t)(m + 8) * HWPIX + n] = r1;
                } else {
                    float* Ob = (float*)OutV + (size_t)b * Odim * HWPIX;
                    float2 r0 = {acc[mf][nf][0] + bv0, acc[mf][nf][1] + bv0};
                    float2 r1 = {acc[mf][nf][2] + bv1, acc[mf][nf][3] + bv1};
                    *(float2*)&Ob[(size_t)m * HWPIX + n] = r0;
                    *(float2*)&Ob[(size_t)(m + 8) * HWPIX + n] = r1;
                }
            }
        }
    }
}

// ---------------------------------------------------------------------------
// Depthwise 3x3 (SAME) on half data, 4 px per thread
// ---------------------------------------------------------------------------
__global__ __launch_bounds__(256) void dwconv_kernel(
    const float* __restrict__ wdw, const float* __restrict__ bdw)
{
    int idx = blockIdx.x * blockDim.x + threadIdx.x;
    if (idx >= BATCH * CDIM * HH * (WW / 4)) return;
    int w0 = (idx % (WW / 4)) * 4;
    int h  = (idx / (WW / 4)) % HH;
    int c  = (idx / (WW / 4 * HH)) % CDIM;
    int b  = idx / (WW / 4 * HH * CDIM);

    const __half* v = g_qkvh + ((size_t)b * 3 * CDIM + 2 * CDIM + c) * HWPIX;

    float r[3][6];
    #pragma unroll
    for (int dy = 0; dy < 3; dy++) {
        int hh = h + dy - 1;
        if (hh >= 0 && hh < HH) {
            const __half* row = v + hh * WW;
            __half2 m0 = *(const __half2*)&row[w0];
            __half2 m1 = *(const __half2*)&row[w0 + 2];
            r[dy][0] = (w0 > 0) ? __half2float(row[w0 - 1]) : 0.f;
            r[dy][1] = __half2float(__low2half(m0));
            r[dy][2] = __half2float(__high2half(m0));
            r[dy][3] = __half2float(__low2half(m1));
            r[dy][4] = __half2float(__high2half(m1));
            r[dy][5] = (w0 + 4 < WW) ? __half2float(row[w0 + 4]) : 0.f;
        } else {
            #pragma unroll
            for (int j = 0; j < 6; j++) r[dy][j] = 0.f;
        }
    }

    float wv[3][3];
    #pragma unroll
    for (int dy = 0; dy < 3; dy++)
        #pragma unroll
        for (int dx = 0; dx < 3; dx++)
            wv[dy][dx] = wdw[c * 9 + dy * 3 + dx];

    float bb = bdw[c];
    float o[4];
    #pragma unroll
    for (int j = 0; j < 4; j++) {
        float s = bb + r[1][j + 1];
        #pragma unroll
        for (int dy = 0; dy < 3; dy++)
            #pragma unroll
            for (int dx = 0; dx < 3; dx++)
                s += wv[dy][dx] * r[dy][j + dx];
        o[j] = s;
    }

    __half* out = g_v2h + ((size_t)b * CDIM + c) * HWPIX + h * WW + w0;
    __half2 o0 = __floats2half2_rn(o[0], o[1]);
    __half2 o1 = __floats2half2_rn(o[2], o[3]);
    *(__half2*)&out[0] = o0;
    *(__half2*)&out[2] = o1;
}

// ---------------------------------------------------------------------------
// FP16 stripe attention, 25 warps (800 threads): ONE 16-row q-tile per warp
// (was 13 warps x 2 rounds). 2x warps/SMSP for latency hiding of the
// S-MMA -> exp -> PV-MMA serial chain. Everything else identical to R8.
// ---------------------------------------------------------------------------
#define KHS 40
#define VTS 408
#define QROWS 400            // 392 + 8 pad rows (zeros)
#define ATT_THREADS 800      // 25 warps
#define ATT_Q_OFF 0
#define ATT_K_OFF (QROWS * KHS)
#define ATT_V_OFF (2 * QROWS * KHS)
#define ATT_O_OFF (2 * QROWS * KHS + HDIM * VTS)
#define ATT_SMEM ((3 * QROWS * KHS + HDIM * VTS) * 2)

__global__ __launch_bounds__(ATT_THREADS, 1) void attn_mma_kernel()
{
    extern __shared__ __half shh[];
    __half* Qsh = shh + ATT_Q_OFF;
    __half* Ksh = shh + ATT_K_OFF;
    __half* Vt  = shh + ATT_V_OFF;
    __half* Osh = shh + ATT_O_OFF;

    const int s = blockIdx.x;
    const int head = blockIdx.y;
    const int b = blockIdx.z;
    const bool wmode = (head >= NHEADS / 2);

    const int tid = threadIdx.x;
    const int wid = tid >> 5;
    const int lane = tid & 31;
    const int lr = lane >> 2;
    const int lc = lane & 3;

    const __half* qbase = g_qkvh + ((size_t)b * 3 * CDIM + head * HDIM) * HWPIX;
    const __half* kbase = g_qkvh + ((size_t)b * 3 * CDIM + CDIM + head * HDIM) * HWPIX;
    const __half* vbase = g_v2h + ((size_t)b * CDIM + head * HDIM) * HWPIX;

    // Stage Q, K, V coalesced (r = pixel-row-major token id)
    for (int idx = tid; idx < NTOK * HDIM; idx += ATT_THREADS) {
        int c = idx / NTOK;
        int r = idx - c * NTOK;
        int pix = wmode ? (r / SWID) * WW + s * SWID + (r % SWID)
                        : s * (SWID * WW) + r;
        size_t g = (size_t)c * HWPIX + pix;
        Qsh[r * KHS + c] = qbase[g];
        Ksh[r * KHS + c] = kbase[g];
        Vt[c * VTS + r] = vbase[g];
    }
    // Zero Q pad rows 392..399
    for (int idx = tid; idx < (QROWS - NTOK) * KHS; idx += ATT_THREADS)
        Qsh[NTOK * KHS + idx] = __half(0.f);
    __syncthreads();

    const int mt = wid;
    if (mt < 25) {
        int q0 = mt * 16;

        uint32_t aq[2][4];
        #pragma unroll
        for (int kf = 0; kf < 2; kf++)
            ldsm_x4(aq[kf], smem_u32(&Qsh[(q0 + (lane & 15)) * KHS +
                                          kf * 16 + (lane >> 4) * 8]));

        float oacc[4][4];
        #pragma unroll
        for (int i = 0; i < 4; i++)
            #pragma unroll
            for (int j = 0; j < 4; j++) oacc[i][j] = 0.f;
        float l0 = 0.f, l1 = 0.f;

        for (int kt = 0; kt < 7; kt++) {
            const int t0 = kt * 56;
            uint32_t pA[3][4];
            uint32_t pA8[2];

            #pragma unroll
            for (int nf = 0; nf < 7; nf++) {
                float sf4[4] = {0.f, 0.f, 0.f, 0.f};
                const __half* kp = &Ksh[(t0 + nf * 8 + lr) * KHS + lc * 2];
                #pragma unroll
                for (int kf = 0; kf < 2; kf++) {
                    uint32_t bfr[2] = {*(const uint32_t*)&kp[kf * 16],
                                       *(const uint32_t*)&kp[kf * 16 + 8]};
                    mma_f16(sf4, aq[kf], bfr);
                }
                float p0 = __expf(fminf(sf4[0] * ATTSCALE, 10.f));
                float p1 = __expf(fminf(sf4[1] * ATTSCALE, 10.f));
                float p2 = __expf(fminf(sf4[2] * ATTSCALE, 10.f));
                float p3 = __expf(fminf(sf4[3] * ATTSCALE, 10.f));
                l0 += p0 + p1;
                l1 += p2 + p3;
                __half2 h01 = __floats2half2_rn(p0, p1);
                __half2 h23 = __floats2half2_rn(p2, p3);
                uint32_t u01 = *(uint32_t*)&h01;
                uint32_t u23 = *(uint32_t*)&h23;
                if (nf == 6) {
                    pA8[0] = u01; pA8[1] = u23;
                } else if ((nf & 1) == 0) {
                    pA[nf >> 1][0] = u01; pA[nf >> 1][1] = u23;
                } else {
                    pA[nf >> 1][2] = u01; pA[nf >> 1][3] = u23;
                }
            }

            #pragma unroll
            for (int ch = 0; ch < 3; ch++) {
                #pragma unroll
                for (int vf = 0; vf < 4; vf++) {
                    const __half* vp = &Vt[(vf * 8 + lr) * VTS + t0 + ch * 16 + lc * 2];
                    uint32_t bfr[2] = {*(const uint32_t*)&vp[0],
                                       *(const uint32_t*)&vp[8]};
                    mma_f16(oacc[vf], pA[ch], bfr);
                }
            }
            #pragma unroll
            for (int vf = 0; vf < 4; vf++) {
                const __half* vp = &Vt[(vf * 8 + lr) * VTS + t0 + 48 + lc * 2];
                mma_f16_k8(oacc[vf], pA8, *(const uint32_t*)&vp[0]);
            }
        }

        l0 += __shfl_xor_sync(0xffffffffu, l0, 1);
        l0 += __shfl_xor_sync(0xffffffffu, l0, 2);
        l1 += __shfl_xor_sync(0xffffffffu, l1, 1);
        l1 += __shfl_xor_sync(0xffffffffu, l1, 2);
        float inv0 = 1.f / l0, inv1 = 1.f / l1;

        int r0 = q0 + lr, r1 = q0 + lr + 8;
        #pragma unroll
        for (int nf = 0; nf < 4; nf++) {
            int c = nf * 8 + 2 * lc;
            __half2 h0 = __floats2half2_rn(oacc[nf][0] * inv0,
                                           oacc[nf][1] * inv0);
            __half2 h1 = __floats2half2_rn(oacc[nf][2] * inv1,
                                           oacc[nf][3] * inv1);
            *(__half2*)&Osh[r0 * KHS + c] = h0;
            *(__half2*)&Osh[r1 * KHS + c] = h1;
        }
    }
    __syncthreads();

    // Coalesced writeback
    __half* obase = g_atth + ((size_t)b * CDIM + head * HDIM) * HWPIX;
    for (int idx = tid; idx < NTOK * HDIM; idx += ATT_THREADS) {
        int c = idx / NTOK;
        int r = idx - c * NTOK;
        int pix = wmode ? (r / SWID) * WW + s * SWID + (r % SWID)
                        : s * (SWID * WW) + r;
        obase[(size_t)c * HWPIX + pix] = Osh[r * KHS + c];
    }
}

// ---------------------------------------------------------------------------
extern "C" void kernel_launch(void* const* d_in, const int* in_sizes, int n_in,
                              void* d_out, int out_size)
{
    const float* x      = (const float*)d_in[0];
    const float* w_qkv  = (const float*)d_in[1];
    const float* b_qkv  = (const float*)d_in[2];
    const float* w_dw   = (const float*)d_in[3];
    const float* b_dw   = (const float*)d_in[4];
    const float* w_proj = (const float*)d_in[5];
    const float* b_proj = (const float*)d_in[6];
    float* out = (float*)d_out;

    __half* xh;   cudaGetSymbolAddress((void**)&xh, g_xh);
    __half* wqh;  cudaGetSymbolAddress((void**)&wqh, g_wqh);
    __half* wph;  cudaGetSymbolAddress((void**)&wph, g_wph);
    __half* qkvh; cudaGetSymbolAddress((void**)&qkvh, g_qkvh);
    __half* atth; cudaGetSymbolAddress((void**)&atth, g_atth);

    cudaFuncSetAttribute(gemm_f16_kernel<true>,
                         cudaFuncAttributeMaxDynamicSharedMemorySize, GEMM_SMEM);
    cudaFuncSetAttribute(gemm_f16_kernel<false>,
                         cudaFuncAttributeMaxDynamicSharedMemorySize, GEMM_SMEM);
    cudaFuncSetAttribute(attn_mma_kernel,
                         cudaFuncAttributeMaxDynamicSharedMemorySize, ATT_SMEM);

    // 0. convert inputs to half
    {
        int n = BATCH * CDIM * HWPIX;
        f2h_kernel<<<(n / 4 + 255) / 256, 256>>>(x, xh, n);
        n = 3 * CDIM * CDIM;
        f2h_kernel<<<(n / 4 + 255) / 256, 256>>>(w_qkv, wqh, n);
        n = CDIM * CDIM;
        f2h_kernel<<<(n / 4 + 255) / 256, 256>>>(w_proj, wph, n);
    }
    // 1. qkv = conv1x1(x) -> half
    {
        dim3 grid((HWPIX + 127) / 128, (3 * CDIM) / 128, BATCH);
        gemm_f16_kernel<true><<<grid, 256, GEMM_SMEM>>>(xh, wqh, b_qkv, qkvh,
                                                        CDIM, 3 * CDIM);
    }
    // 2. v2 = v + dwconv(v)
    {
        int n = BATCH * CDIM * HH * (WW / 4);
        dwconv_kernel<<<(n + 255) / 256, 256>>>(w_dw, b_dw);
    }
    // 3. fp16 stripe attention -> half
    {
        dim3 grid(NSTRIPE, NHEADS, BATCH);
        attn_mma_kernel<<<grid, ATT_THREADS, ATT_SMEM>>>();
    }
    // 4. out = conv1x1(att) -> fp32
    {
        dim3 grid((HWPIX + 127) / 128, CDIM / 128, BATCH);
        gemm_f16_kernel<false><<<grid, 256, GEMM_SMEM>>>(atth, wph, b_proj, out,
                                                         CDIM, CDIM);
    }
}